// round 8
// baseline (speedup 1.0000x reference)
#include <cuda_runtime.h>
#include <cuda_fp16.h>
#include <cuda_bf16.h>
#include <math_constants.h>
#include <cstdint>

#define ENC_DIM 256
#define INT_DIM 256
#define MT 128                  // rows per CTA (M)
#define NTILE 128               // hidden per CTA (N) -- split across 2 CTAs
#define KC 32                   // k per staged chunk
#define NCHUNK (ENC_DIM / KC)   // 8
#define NKS (KC / 16)           // 2 k16 steps per chunk
#define P 20                    // smem pitch in u32 words (16 used + 4 pad)
#define ASZ (MT * P)            // 2560 words
#define BSZ (NTILE * P)         // 2560 words
#define DYN_BYTES (2 * (ASZ + BSZ) * 4)   // 40960 -> 2 CTAs/SM
#define NTHR 256
#define NC 16                   // context chunks per batch

// Scratch (allocation-free rule: __device__ globals)
__device__ float  g_dp[64 * INT_DIM];          // dec_proj [B, I]
__device__ float  g_scores[2 * 64 * 2048];     // partial scores [nh][B*T]
__device__ float  g_w2t[ENC_DIM * INT_DIM];    // w2 transposed
__device__ __half g_w1h[INT_DIM * ENC_DIM];    // w1 as fp16, [n][k]
__device__ float  g_part[NC * 64 * ENC_DIM];   // context partials

// ---------------------------------------------------------------------------
// helpers
// ---------------------------------------------------------------------------
__device__ __forceinline__ float tanha(float x) {
    float y;
    asm("tanh.approx.f32 %0, %1;" : "=f"(y) : "f"(x));
    return y;
}
__device__ __forceinline__ void cp16(unsigned dst_s, const void* src) {
    asm volatile("cp.async.cg.shared.global [%0], [%1], 16;"
                 :: "r"(dst_s), "l"(src) : "memory");
}
__device__ __forceinline__ void cp_commit() {
    asm volatile("cp.async.commit_group;" ::: "memory");
}
template <int N>
__device__ __forceinline__ void cp_wait() {
    asm volatile("cp.async.wait_group %0;" :: "n"(N) : "memory");
}
__device__ __forceinline__ unsigned s2u(const void* p) {
    return (unsigned)__cvta_generic_to_shared(p);
}
__device__ __forceinline__ void mma_f16(float d[4], const unsigned a[4],
                                        unsigned b0, unsigned b1) {
    asm volatile(
        "mma.sync.aligned.m16n8k16.row.col.f32.f16.f16.f32 "
        "{%0,%1,%2,%3}, {%4,%5,%6,%7}, {%8,%9}, {%0,%1,%2,%3};"
        : "+f"(d[0]), "+f"(d[1]), "+f"(d[2]), "+f"(d[3])
        : "r"(a[0]), "r"(a[1]), "r"(a[2]), "r"(a[3]), "r"(b0), "r"(b1));
}

// ---------------------------------------------------------------------------
// K0a: w1 -> fp16 (layout unchanged: [n][k])
// ---------------------------------------------------------------------------
__global__ void w1half_kernel(const float* __restrict__ w1,
                              __half* __restrict__ w1h) {
    const int i = blockIdx.x * 256 + threadIdx.x;
    w1h[i] = __float2half(w1[i]);
}

// ---------------------------------------------------------------------------
// K0b: transpose w2 (for decproj coalescing)
// ---------------------------------------------------------------------------
__global__ void transpose_w2_kernel(const float* __restrict__ w2,
                                    float* __restrict__ w2t) {
    __shared__ float tile[32][33];
    int x = blockIdx.x * 32 + threadIdx.x;
    int y = blockIdx.y * 32 + threadIdx.y;
#pragma unroll
    for (int dy = 0; dy < 32; dy += 8)
        tile[threadIdx.y + dy][threadIdx.x] = w2[(y + dy) * 256 + x];
    __syncthreads();
    x = blockIdx.y * 32 + threadIdx.x;
    y = blockIdx.x * 32 + threadIdx.y;
#pragma unroll
    for (int dy = 0; dy < 32; dy += 8)
        w2t[(y + dy) * 256 + x] = tile[threadIdx.x][threadIdx.y + dy];
}

// ---------------------------------------------------------------------------
// K1: dec_proj[b,i] = sum_k w2t[k,i] * dec[b,k]
// ---------------------------------------------------------------------------
__global__ void decproj_kernel(const float* __restrict__ dec,
                               const float* __restrict__ w2t,
                               float* __restrict__ dp) {
    __shared__ float ds[ENC_DIM];
    const int b = blockIdx.x;
    const int i = threadIdx.x;
    ds[i] = dec[b * ENC_DIM + i];
    __syncthreads();
    float acc = 0.f;
#pragma unroll 8
    for (int k = 0; k < ENC_DIM; ++k)
        acc = fmaf(__ldg(w2t + k * INT_DIM + i), ds[k], acc);
    dp[b * INT_DIM + i] = acc;
}

// ---------------------------------------------------------------------------
// K2: scores via fp16 mma m16n8k16. CTA = 128 rows x 128 n (N split 2-way),
// 256 threads, 2 CTAs/SM for cross-CTA phase overlap.
// bid: rowtile = bid>>1, nhalf = bid&1 (adjacent bids share enc rows -> L2).
// Warp w: m-group (w&3)*32 (h=2, B reused), n-quarter (w>>2)*64 (j=8).
// Writes partial scores to plane nhalf; softmax sums the planes.
// ---------------------------------------------------------------------------
__global__ void __launch_bounds__(NTHR, 2)
scores_mma_kernel(const float* __restrict__ enc,
                  const __half* __restrict__ w1h,
                  const float* __restrict__ dp,
                  const float* __restrict__ v,
                  float* __restrict__ scores2,
                  int T, int BT) {
    extern __shared__ unsigned sm[];          // A0 | A1 | B0 | B1
    __shared__ float dps[NTILE], vs[NTILE], ssc[MT];

    const int tid  = threadIdx.x;
    const int wid  = tid >> 5;
    const int lane = tid & 31;
    const int g    = lane >> 2;
    const int t    = lane & 3;
    const int m0   = (wid & 3) * 32;
    const int nq   = (wid >> 2) * 64;         // n-quarter within CTA's 128
    const int nh   = blockIdx.x & 1;
    const int n0g  = nh * NTILE;               // global n offset
    const long long row0 = (long long)(blockIdx.x >> 1) * MT;
    const int b = (int)(row0 / T);

    if (tid < NTILE) {
        dps[tid] = dp[b * INT_DIM + n0g + tid];
        vs[tid]  = __ldg(v + n0g + tid);
    }
    if (tid < MT) ssc[tid] = 0.f;

    const unsigned smem_base = s2u(sm);
    const int ar = tid >> 1;                  // A staging: row (0..127)
    const int ah = tid & 1;                   // A staging: half (16 floats)

    // stage B chunk c into buffer c&1 via cp.async (512 cp16 / 256 thr = 2)
    auto stageB = [&](int c) {
        const int kc = c * KC;
        const unsigned bb = smem_base + (2 * ASZ + (c & 1) * BSZ) * 4;
#pragma unroll
        for (int i = tid; i < NTILE * 4; i += NTHR) {
            int n = i >> 2, q = i & 3;
            cp16(bb + (n * P + q * 4) * 4,
                 w1h + (n0g + n) * ENC_DIM + kc + q * 8);
        }
    };

    float4 fr[4];                              // A prefetch regs (16 floats)
    auto ldgA = [&](int c) {
        const float4* src = reinterpret_cast<const float4*>(
            enc + (row0 + ar) * ENC_DIM + c * KC + ah * 16);
        fr[0] = src[0]; fr[1] = src[1]; fr[2] = src[2]; fr[3] = src[3];
    };
    auto stsA = [&](int c) {
        uint32_t w[8];
#pragma unroll
        for (int q = 0; q < 4; ++q) {
            __half2 h0 = __floats2half2_rn(fr[q].x, fr[q].y);
            __half2 h1 = __floats2half2_rn(fr[q].z, fr[q].w);
            w[2 * q]     = *reinterpret_cast<uint32_t*>(&h0);
            w[2 * q + 1] = *reinterpret_cast<uint32_t*>(&h1);
        }
        uint4* dst = reinterpret_cast<uint4*>(
            sm + (c & 1) * ASZ + ar * P + ah * 8);
        dst[0] = make_uint4(w[0], w[1], w[2], w[3]);
        dst[1] = make_uint4(w[4], w[5], w[6], w[7]);
    };

    float d[2][8][4];
#pragma unroll
    for (int h = 0; h < 2; ++h)
#pragma unroll
        for (int j = 0; j < 8; ++j)
#pragma unroll
            for (int q = 0; q < 4; ++q) d[h][j][q] = 0.f;

    // prologue: B0,B1 in flight; A0 staged; regs hold A1
    stageB(0); cp_commit();
    stageB(1); cp_commit();
    ldgA(0);
    stsA(0);
    ldgA(1);
    cp_wait<1>();                              // B0 arrived
    __syncthreads();

    for (int c = 0; c < NCHUNK; ++c) {
        const int p = c & 1;
        const unsigned* as = sm + p * ASZ;
        const unsigned* bs = sm + 2 * ASZ + p * BSZ;

#pragma unroll
        for (int s = 0; s < NKS; ++s) {        // two k16 steps per chunk
            unsigned a[2][4];
#pragma unroll
            for (int h = 0; h < 2; ++h) {
                const int r = m0 + 16 * h + g;
                a[h][0] = as[r * P + s * 8 + t];
                a[h][1] = as[(r + 8) * P + s * 8 + t];
                a[h][2] = as[r * P + s * 8 + t + 4];
                a[h][3] = as[(r + 8) * P + s * 8 + t + 4];
            }
            const unsigned* b0p = bs + (nq + g) * P + s * 8 + t;
#pragma unroll
            for (int j = 0; j < 8; ++j) {
                unsigned b0 = b0p[8 * j * P];
                unsigned b1 = b0p[8 * j * P + 4];
                mma_f16(d[0][j], a[0], b0, b1);
                mma_f16(d[1][j], a[1], b0, b1);
            }
        }

        if (c + 1 < NCHUNK) stsA(c + 1);       // writes buffer 1-p: safe
        __syncthreads();                        // chunk c fully consumed
        if (c + 2 < NCHUNK) {
            ldgA(c + 2);
            stageB(c + 2); cp_commit();        // writes buffer p: now safe
            cp_wait<1>();                      // B(c+1) arrived
        } else {
            cp_wait<0>();
        }
        __syncthreads();                        // staged data visible to all
    }

    // Epilogue: +dec_proj, tanh.approx, *v, warp-reduce n, 2-way smem combine
#pragma unroll
    for (int h = 0; h < 2; ++h) {
        float s0 = 0.f, s1 = 0.f;
#pragma unroll
        for (int j = 0; j < 8; ++j) {
            const int n0 = nq + 8 * j + 2 * t;
            const float vv0 = vs[n0],  vv1 = vs[n0 + 1];
            const float dd0 = dps[n0], dd1 = dps[n0 + 1];
            s0 += vv0 * tanha(d[h][j][0] + dd0) + vv1 * tanha(d[h][j][1] + dd1);
            s1 += vv0 * tanha(d[h][j][2] + dd0) + vv1 * tanha(d[h][j][3] + dd1);
        }
        s0 += __shfl_xor_sync(0xffffffffu, s0, 1);
        s0 += __shfl_xor_sync(0xffffffffu, s0, 2);
        s1 += __shfl_xor_sync(0xffffffffu, s1, 1);
        s1 += __shfl_xor_sync(0xffffffffu, s1, 2);
        if (t == 0) {
            atomicAdd(&ssc[m0 + 16 * h + g], s0);       // 2 adders/row: exact
            atomicAdd(&ssc[m0 + 16 * h + 8 + g], s1);
        }
    }
    __syncthreads();
    if (tid < MT) scores2[(long long)nh * BT + row0 + tid] = ssc[tid];
}

// ---------------------------------------------------------------------------
// K3: per-batch softmax over T (sums the two partial-score planes) -> probs
// ---------------------------------------------------------------------------
__global__ void softmax_kernel(const float* __restrict__ scores2,
                               float* __restrict__ out,
                               int B, int T) {
    extern __shared__ float ss[];
    __shared__ float red[8];
    const int b = blockIdx.x;
    const int tid = threadIdx.x;
    const int lane = tid & 31, wid = tid >> 5;
    const int BT = B * T;

    for (int t = tid; t < T; t += 256)
        ss[t] = scores2[b * T + t] + scores2[BT + b * T + t];
    __syncthreads();

    float m = -CUDART_INF_F;
    for (int t = tid; t < T; t += 256) m = fmaxf(m, ss[t]);
#pragma unroll
    for (int o = 16; o; o >>= 1) m = fmaxf(m, __shfl_xor_sync(0xffffffffu, m, o));
    if (lane == 0) red[wid] = m;
    __syncthreads();
    if (tid == 0) {
        float mm = red[0];
#pragma unroll
        for (int w = 1; w < 8; ++w) mm = fmaxf(mm, red[w]);
        red[0] = mm;
    }
    __syncthreads();
    m = red[0];
    __syncthreads();

    float z = 0.f;
    for (int t = tid; t < T; t += 256) z += expf(ss[t] - m);
#pragma unroll
    for (int o = 16; o; o >>= 1) z += __shfl_xor_sync(0xffffffffu, z, o);
    if (lane == 0) red[wid] = z;
    __syncthreads();
    if (tid == 0) {
        float zz = 0.f;
#pragma unroll
        for (int w = 0; w < 8; ++w) zz += red[w];
        red[0] = zz;
    }
    __syncthreads();
    const float inv = 1.f / red[0];

    float* probs = out + (long long)B * ENC_DIM;
    for (int t = tid; t < T; t += 256)
        probs[(long long)b * T + t] = expf(ss[t] - m) * inv;
}

// ---------------------------------------------------------------------------
// K4: context partials. grid (B, NC). 4 accumulators for MLP.
// ---------------------------------------------------------------------------
__global__ void ctx_partial_kernel(const float* __restrict__ enc,
                                   const float* __restrict__ out_probs,
                                   float* __restrict__ part,
                                   int B, int T) {
    __shared__ float ps[2048 / NC];
    const int b = blockIdx.x;
    const int c = blockIdx.y;
    const int tid = threadIdx.x;
    const int TC = T / NC;                       // 128
    const long long t0 = (long long)c * TC;

    if (tid < TC) ps[tid] = out_probs[(long long)b * T + t0 + tid];
    __syncthreads();

    float a0 = 0.f, a1 = 0.f, a2 = 0.f, a3 = 0.f;
    const float* e = enc + ((long long)b * T + t0) * ENC_DIM + tid;
#pragma unroll 8
    for (int t = 0; t < TC; t += 4) {
        a0 = fmaf(ps[t],     __ldg(e + (long long)t * ENC_DIM),       a0);
        a1 = fmaf(ps[t + 1], __ldg(e + (long long)(t + 1) * ENC_DIM), a1);
        a2 = fmaf(ps[t + 2], __ldg(e + (long long)(t + 2) * ENC_DIM), a2);
        a3 = fmaf(ps[t + 3], __ldg(e + (long long)(t + 3) * ENC_DIM), a3);
    }
    part[((long long)c * B + b) * ENC_DIM + tid] = (a0 + a1) + (a2 + a3);
}

// ---------------------------------------------------------------------------
// K5: reduce partials -> out context region
// ---------------------------------------------------------------------------
__global__ void ctx_reduce_kernel(const float* __restrict__ part,
                                  float* __restrict__ out, int B) {
    const int b = blockIdx.x;
    const int tid = threadIdx.x;
    float acc = 0.f;
#pragma unroll
    for (int c = 0; c < NC; ++c)
        acc += part[((long long)c * B + b) * ENC_DIM + tid];
    out[b * ENC_DIM + tid] = acc;
}

// ---------------------------------------------------------------------------
extern "C" void kernel_launch(void* const* d_in, const int* in_sizes, int n_in,
                              void* d_out, int out_size) {
    const float* enc = (const float*)d_in[0];   // [B,T,256]
    const float* dec = (const float*)d_in[1];   // [B,256]
    const float* w1  = (const float*)d_in[2];   // [256,256]
    const float* w2  = (const float*)d_in[3];   // [256,256]
    const float* v   = (const float*)d_in[4];   // [1,256]
    float* out = (float*)d_out;

    const int B = in_sizes[1] / ENC_DIM;                 // 64
    const int T = in_sizes[0] / (B * ENC_DIM);           // 2048

    float*  dp_ptr;     cudaGetSymbolAddress((void**)&dp_ptr, g_dp);
    float*  scores_ptr; cudaGetSymbolAddress((void**)&scores_ptr, g_scores);
    float*  w2t_ptr;    cudaGetSymbolAddress((void**)&w2t_ptr, g_w2t);
    __half* w1h_ptr;    cudaGetSymbolAddress((void**)&w1h_ptr, g_w1h);
    float*  part_ptr;   cudaGetSymbolAddress((void**)&part_ptr, g_part);

    cudaFuncSetAttribute(scores_mma_kernel,
                         cudaFuncAttributeMaxDynamicSharedMemorySize, DYN_BYTES);

    w1half_kernel<<<INT_DIM * ENC_DIM / 256, 256>>>(w1, w1h_ptr);
    transpose_w2_kernel<<<dim3(8, 8), dim3(32, 8)>>>(w2, w2t_ptr);
    decproj_kernel<<<B, 256>>>(dec, w2t_ptr, dp_ptr);
    scores_mma_kernel<<<2 * (B * T) / MT, NTHR, DYN_BYTES>>>(
        enc, w1h_ptr, dp_ptr, v, scores_ptr, T, B * T);
    softmax_kernel<<<B, 256, T * (int)sizeof(float)>>>(scores_ptr, out, B, T);
    ctx_partial_kernel<<<dim3(B, NC), 256>>>(enc, out + (long long)B * ENC_DIM,
                                             part_ptr, B, T);
    ctx_reduce_kernel<<<B, 256>>>(part_ptr, out, B);
}

// round 9
// speedup vs baseline: 1.1542x; 1.1542x over previous
#include <cuda_runtime.h>
#include <cuda_fp16.h>
#include <cuda_bf16.h>
#include <math_constants.h>
#include <cstdint>

#define ENC_DIM 256
#define INT_DIM 256
#define MT 128                  // rows per CTA (M)
#define NT 256                  // hidden per CTA (N)
#define KC 64                   // k per staged chunk
#define NCHUNK (ENC_DIM / KC)   // 4
#define NKS (KC / 16)           // 4 k16 steps per chunk
#define P 36                    // smem pitch in u32 words (32 used + 4 pad)
#define ASZ (MT * P)            // 4608 words
#define BSZ (NT * P)            // 9216 words
#define DYN_BYTES (2 * (ASZ + BSZ) * 4)   // 110592
#define NTHR 512
#define NC 16                   // context chunks per batch

// Scratch (allocation-free rule: __device__ globals)
__device__ float  g_dp[64 * INT_DIM];          // dec_proj [B, I]
__device__ float  g_scores[64 * 2048];         // scores   [B, T]
__device__ float  g_w2t[ENC_DIM * INT_DIM];    // w2 transposed
__device__ __half g_w1h[INT_DIM * ENC_DIM];    // w1 as fp16, [n][k]
__device__ float  g_part[NC * 64 * ENC_DIM];   // context partials

// ---------------------------------------------------------------------------
// helpers
// ---------------------------------------------------------------------------
__device__ __forceinline__ float tanha(float x) {
    float y;
    asm("tanh.approx.f32 %0, %1;" : "=f"(y) : "f"(x));
    return y;
}
__device__ __forceinline__ void cp16(unsigned dst_s, const void* src) {
    asm volatile("cp.async.cg.shared.global [%0], [%1], 16;"
                 :: "r"(dst_s), "l"(src) : "memory");
}
__device__ __forceinline__ void cp_commit() {
    asm volatile("cp.async.commit_group;" ::: "memory");
}
template <int N>
__device__ __forceinline__ void cp_wait() {
    asm volatile("cp.async.wait_group %0;" :: "n"(N) : "memory");
}
__device__ __forceinline__ unsigned s2u(const void* p) {
    return (unsigned)__cvta_generic_to_shared(p);
}
__device__ __forceinline__ void ldsm4(unsigned r[4], unsigned addr) {
    asm volatile("ldmatrix.sync.aligned.m8n8.x4.shared.b16 "
                 "{%0,%1,%2,%3}, [%4];"
                 : "=r"(r[0]), "=r"(r[1]), "=r"(r[2]), "=r"(r[3])
                 : "r"(addr));
}
__device__ __forceinline__ void mma_f16(float d[4], const unsigned a[4],
                                        unsigned b0, unsigned b1) {
    asm volatile(
        "mma.sync.aligned.m16n8k16.row.col.f32.f16.f16.f32 "
        "{%0,%1,%2,%3}, {%4,%5,%6,%7}, {%8,%9}, {%0,%1,%2,%3};"
        : "+f"(d[0]), "+f"(d[1]), "+f"(d[2]), "+f"(d[3])
        : "r"(a[0]), "r"(a[1]), "r"(a[2]), "r"(a[3]), "r"(b0), "r"(b1));
}

// ---------------------------------------------------------------------------
// K0a: w1 -> fp16 (layout unchanged: [n][k])
// ---------------------------------------------------------------------------
__global__ void w1half_kernel(const float* __restrict__ w1,
                              __half* __restrict__ w1h) {
    const int i = blockIdx.x * 256 + threadIdx.x;
    w1h[i] = __float2half(w1[i]);
}

// ---------------------------------------------------------------------------
// K0b: transpose w2 (for decproj coalescing)
// ---------------------------------------------------------------------------
__global__ void transpose_w2_kernel(const float* __restrict__ w2,
                                    float* __restrict__ w2t) {
    __shared__ float tile[32][33];
    int x = blockIdx.x * 32 + threadIdx.x;
    int y = blockIdx.y * 32 + threadIdx.y;
#pragma unroll
    for (int dy = 0; dy < 32; dy += 8)
        tile[threadIdx.y + dy][threadIdx.x] = w2[(y + dy) * 256 + x];
    __syncthreads();
    x = blockIdx.y * 32 + threadIdx.x;
    y = blockIdx.x * 32 + threadIdx.y;
#pragma unroll
    for (int dy = 0; dy < 32; dy += 8)
        w2t[(y + dy) * 256 + x] = tile[threadIdx.x][threadIdx.y + dy];
}

// ---------------------------------------------------------------------------
// K1: dec_proj[b,i] = sum_k w2t[k,i] * dec[b,k]
// ---------------------------------------------------------------------------
__global__ void decproj_kernel(const float* __restrict__ dec,
                               const float* __restrict__ w2t,
                               float* __restrict__ dp) {
    __shared__ float ds[ENC_DIM];
    const int b = blockIdx.x;
    const int i = threadIdx.x;
    ds[i] = dec[b * ENC_DIM + i];
    __syncthreads();
    float acc = 0.f;
#pragma unroll 8
    for (int k = 0; k < ENC_DIM; ++k)
        acc = fmaf(__ldg(w2t + k * INT_DIM + i), ds[k], acc);
    dp[b * INT_DIM + i] = acc;
}

// ---------------------------------------------------------------------------
// K2: scores via fp16 mma m16n8k16 + ldmatrix fragment loads.
// Block = 128 rows x 256 n, 512 threads, K=256 in 4 chunks of 64.
// Warp w: m-group (w&3)*32 (h=2, B reused), n-quarter (w>>2)*64 (j=8).
// Per k16 step: 2 A-LDSM.x4 + 4 B-LDSM.x4 + 16 HMMA (was 24 scalar LDS).
// ---------------------------------------------------------------------------
__global__ void __launch_bounds__(NTHR, 1)
scores_mma_kernel(const float* __restrict__ enc,
                  const __half* __restrict__ w1h,
                  const float* __restrict__ dp,
                  const float* __restrict__ v,
                  float* __restrict__ scores,
                  int T) {
    extern __shared__ unsigned sm[];          // A0 | A1 | B0 | B1
    __shared__ float dps[INT_DIM], vs[INT_DIM], ssc[MT];

    const int tid  = threadIdx.x;
    const int wid  = tid >> 5;
    const int lane = tid & 31;
    const int t    = lane & 3;
    const int m0   = (wid & 3) * 32;
    const int nb   = (wid >> 2) * 64;
    const long long row0 = (long long)blockIdx.x * MT;
    const int b = (int)(row0 / T);

    if (tid < INT_DIM) {
        dps[tid] = dp[b * INT_DIM + tid];
        vs[tid]  = __ldg(v + tid);
    }
    if (tid < MT) ssc[tid] = 0.f;

    const unsigned smem_base = s2u(sm);

    // ldmatrix lane-dependent word offsets (within a buffer)
    // A x4 (per h): M0=rows m0..+7 k0-7, M1=rows+8 k0-7, M2=rows k8-15, M3=rows+8 k8-15
    const unsigned a_lane_off = (unsigned)((m0 + (lane & 15)) * P + ((lane >> 4) << 2));
    // B x4 (per j-pair): M0=rows(j) k0-7, M1=rows(j) k8-15, M2=rows(j+1) k0-7, M3=rows(j+1) k8-15
    const unsigned b_lane_off = (unsigned)((nb + ((lane >> 4) & 1) * 8 + (lane & 7)) * P
                                           + ((lane >> 3) & 1) * 4);

    const int ar = tid >> 2;                  // A staging: row (0..127)
    const int aq = tid & 3;                   // A staging: quarter (16 floats)

    // stage B chunk c into buffer c&1 via cp.async
    auto stageB = [&](int c) {
        const int kc = c * KC;
        const unsigned bb = smem_base + (2 * ASZ + (c & 1) * BSZ) * 4;
#pragma unroll
        for (int i = tid; i < NT * 8; i += NTHR) {
            int n = i >> 3, q = i & 7;
            cp16(bb + (n * P + q * 4) * 4, w1h + n * ENC_DIM + kc + q * 8);
        }
    };

    float4 fr[4];                              // A prefetch regs (16 floats)
    auto ldgA = [&](int c) {
        const float4* src = reinterpret_cast<const float4*>(
            enc + (row0 + ar) * ENC_DIM + c * KC + aq * 16);
        fr[0] = src[0]; fr[1] = src[1]; fr[2] = src[2]; fr[3] = src[3];
    };
    auto stsA = [&](int c) {
        uint32_t w[8];
#pragma unroll
        for (int q = 0; q < 4; ++q) {
            __half2 h0 = __floats2half2_rn(fr[q].x, fr[q].y);
            __half2 h1 = __floats2half2_rn(fr[q].z, fr[q].w);
            w[2 * q]     = *reinterpret_cast<uint32_t*>(&h0);
            w[2 * q + 1] = *reinterpret_cast<uint32_t*>(&h1);
        }
        uint4* dst = reinterpret_cast<uint4*>(
            sm + (c & 1) * ASZ + ar * P + aq * 8);
        dst[0] = make_uint4(w[0], w[1], w[2], w[3]);
        dst[1] = make_uint4(w[4], w[5], w[6], w[7]);
    };

    float d[2][8][4];
#pragma unroll
    for (int h = 0; h < 2; ++h)
#pragma unroll
        for (int j = 0; j < 8; ++j)
#pragma unroll
            for (int q = 0; q < 4; ++q) d[h][j][q] = 0.f;

    // prologue: B0,B1 in flight; A0 staged; regs hold A1
    stageB(0); cp_commit();
    stageB(1); cp_commit();
    ldgA(0);
    stsA(0);
    ldgA(1);
    cp_wait<1>();                              // B0 arrived
    __syncthreads();

    for (int c = 0; c < NCHUNK; ++c) {
        const int p = c & 1;
        const unsigned abase = smem_base + (p * ASZ) * 4 + a_lane_off * 4;
        const unsigned bbase = smem_base + (2 * ASZ + p * BSZ) * 4 + b_lane_off * 4;

#pragma unroll
        for (int s = 0; s < NKS; ++s) {        // four k16 steps per chunk
            unsigned a[2][4];
            ldsm4(a[0], abase + (s * 8) * 4);
            ldsm4(a[1], abase + (16 * P + s * 8) * 4);
#pragma unroll
            for (int jp = 0; jp < 4; ++jp) {   // j-pairs {0,1},{2,3},{4,5},{6,7}
                unsigned bb[4];
                ldsm4(bb, bbase + (jp * 16 * P + s * 8) * 4);
                mma_f16(d[0][2 * jp],     a[0], bb[0], bb[1]);
                mma_f16(d[1][2 * jp],     a[1], bb[0], bb[1]);
                mma_f16(d[0][2 * jp + 1], a[0], bb[2], bb[3]);
                mma_f16(d[1][2 * jp + 1], a[1], bb[2], bb[3]);
            }
        }

        if (c + 1 < NCHUNK) stsA(c + 1);       // writes buffer 1-p: safe
        __syncthreads();                        // chunk c fully consumed
        if (c + 2 < NCHUNK) {
            ldgA(c + 2);
            stageB(c + 2); cp_commit();        // writes buffer p: now safe
            cp_wait<1>();                      // B(c+1) arrived
        } else {
            cp_wait<0>();
        }
        __syncthreads();                        // staged data visible to all
    }

    // Epilogue: +dec_proj, tanh.approx, *v, warp-reduce n, 4-way smem combine
    const int g = lane >> 2;
#pragma unroll
    for (int h = 0; h < 2; ++h) {
        float s0 = 0.f, s1 = 0.f;
#pragma unroll
        for (int j = 0; j < 8; ++j) {
            const int n0 = nb + 8 * j + 2 * t;
            const float vv0 = vs[n0],  vv1 = vs[n0 + 1];
            const float dd0 = dps[n0], dd1 = dps[n0 + 1];
            s0 += vv0 * tanha(d[h][j][0] + dd0) + vv1 * tanha(d[h][j][1] + dd1);
            s1 += vv0 * tanha(d[h][j][2] + dd0) + vv1 * tanha(d[h][j][3] + dd1);
        }
        s0 += __shfl_xor_sync(0xffffffffu, s0, 1);
        s0 += __shfl_xor_sync(0xffffffffu, s0, 2);
        s1 += __shfl_xor_sync(0xffffffffu, s1, 1);
        s1 += __shfl_xor_sync(0xffffffffu, s1, 2);
        if (t == 0) {
            atomicAdd(&ssc[m0 + 16 * h + g], s0);
            atomicAdd(&ssc[m0 + 16 * h + 8 + g], s1);
        }
    }
    __syncthreads();
    if (tid < MT) scores[row0 + tid] = ssc[tid];
}

// ---------------------------------------------------------------------------
// K3: per-batch softmax over T -> probs (out[B*256 ..])
// ---------------------------------------------------------------------------
__global__ void softmax_kernel(const float* __restrict__ scores,
                               float* __restrict__ out,
                               int B, int T) {
    extern __shared__ float ss[];
    __shared__ float red[8];
    const int b = blockIdx.x;
    const int tid = threadIdx.x;
    const int lane = tid & 31, wid = tid >> 5;

    for (int t = tid; t < T; t += 256) ss[t] = scores[b * T + t];
    __syncthreads();

    float m = -CUDART_INF_F;
    for (int t = tid; t < T; t += 256) m = fmaxf(m, ss[t]);
#pragma unroll
    for (int o = 16; o; o >>= 1) m = fmaxf(m, __shfl_xor_sync(0xffffffffu, m, o));
    if (lane == 0) red[wid] = m;
    __syncthreads();
    if (tid == 0) {
        float mm = red[0];
#pragma unroll
        for (int w = 1; w < 8; ++w) mm = fmaxf(mm, red[w]);
        red[0] = mm;
    }
    __syncthreads();
    m = red[0];
    __syncthreads();

    float z = 0.f;
    for (int t = tid; t < T; t += 256) z += expf(ss[t] - m);
#pragma unroll
    for (int o = 16; o; o >>= 1) z += __shfl_xor_sync(0xffffffffu, z, o);
    if (lane == 0) red[wid] = z;
    __syncthreads();
    if (tid == 0) {
        float zz = 0.f;
#pragma unroll
        for (int w = 0; w < 8; ++w) zz += red[w];
        red[0] = zz;
    }
    __syncthreads();
    const float inv = 1.f / red[0];

    float* probs = out + (long long)B * ENC_DIM;
    for (int t = tid; t < T; t += 256)
        probs[(long long)b * T + t] = expf(ss[t] - m) * inv;
}

// ---------------------------------------------------------------------------
// K4: context partials. grid (B, NC). 4 accumulators for MLP.
// ---------------------------------------------------------------------------
__global__ void ctx_partial_kernel(const float* __restrict__ enc,
                                   const float* __restrict__ out_probs,
                                   float* __restrict__ part,
                                   int B, int T) {
    __shared__ float ps[2048 / NC];
    const int b = blockIdx.x;
    const int c = blockIdx.y;
    const int tid = threadIdx.x;
    const int TC = T / NC;                       // 128
    const long long t0 = (long long)c * TC;

    if (tid < TC) ps[tid] = out_probs[(long long)b * T + t0 + tid];
    __syncthreads();

    float a0 = 0.f, a1 = 0.f, a2 = 0.f, a3 = 0.f;
    const float* e = enc + ((long long)b * T + t0) * ENC_DIM + tid;
#pragma unroll 8
    for (int t = 0; t < TC; t += 4) {
        a0 = fmaf(ps[t],     __ldg(e + (long long)t * ENC_DIM),       a0);
        a1 = fmaf(ps[t + 1], __ldg(e + (long long)(t + 1) * ENC_DIM), a1);
        a2 = fmaf(ps[t + 2], __ldg(e + (long long)(t + 2) * ENC_DIM), a2);
        a3 = fmaf(ps[t + 3], __ldg(e + (long long)(t + 3) * ENC_DIM), a3);
    }
    part[((long long)c * B + b) * ENC_DIM + tid] = (a0 + a1) + (a2 + a3);
}

// ---------------------------------------------------------------------------
// K5: reduce partials -> out context region
// ---------------------------------------------------------------------------
__global__ void ctx_reduce_kernel(const float* __restrict__ part,
                                  float* __restrict__ out, int B) {
    const int b = blockIdx.x;
    const int tid = threadIdx.x;
    float acc = 0.f;
#pragma unroll
    for (int c = 0; c < NC; ++c)
        acc += part[((long long)c * B + b) * ENC_DIM + tid];
    out[b * ENC_DIM + tid] = acc;
}

// ---------------------------------------------------------------------------
extern "C" void kernel_launch(void* const* d_in, const int* in_sizes, int n_in,
                              void* d_out, int out_size) {
    const float* enc = (const float*)d_in[0];   // [B,T,256]
    const float* dec = (const float*)d_in[1];   // [B,256]
    const float* w1  = (const float*)d_in[2];   // [256,256]
    const float* w2  = (const float*)d_in[3];   // [256,256]
    const float* v   = (const float*)d_in[4];   // [1,256]
    float* out = (float*)d_out;

    const int B = in_sizes[1] / ENC_DIM;                 // 64
    const int T = in_sizes[0] / (B * ENC_DIM);           // 2048

    float*  dp_ptr;     cudaGetSymbolAddress((void**)&dp_ptr, g_dp);
    float*  scores_ptr; cudaGetSymbolAddress((void**)&scores_ptr, g_scores);
    float*  w2t_ptr;    cudaGetSymbolAddress((void**)&w2t_ptr, g_w2t);
    __half* w1h_ptr;    cudaGetSymbolAddress((void**)&w1h_ptr, g_w1h);
    float*  part_ptr;   cudaGetSymbolAddress((void**)&part_ptr, g_part);

    cudaFuncSetAttribute(scores_mma_kernel,
                         cudaFuncAttributeMaxDynamicSharedMemorySize, DYN_BYTES);

    w1half_kernel<<<INT_DIM * ENC_DIM / 256, 256>>>(w1, w1h_ptr);
    transpose_w2_kernel<<<dim3(8, 8), dim3(32, 8)>>>(w2, w2t_ptr);
    decproj_kernel<<<B, 256>>>(dec, w2t_ptr, dp_ptr);
    scores_mma_kernel<<<(B * T) / MT, NTHR, DYN_BYTES>>>(enc, w1h_ptr, dp_ptr, v,
                                                         scores_ptr, T);
    softmax_kernel<<<B, 256, T * (int)sizeof(float)>>>(scores_ptr, out, B, T);
    ctx_partial_kernel<<<dim3(B, NC), 256>>>(enc, out + (long long)B * ENC_DIM,
                                             part_ptr, B, T);
    ctx_reduce_kernel<<<B, 256>>>(part_ptr, out, B);
}

// round 10
// speedup vs baseline: 1.1766x; 1.0194x over previous
#include <cuda_runtime.h>
#include <cuda_fp16.h>
#include <cuda_bf16.h>
#include <math_constants.h>
#include <cstdint>

#define ENC_DIM 256
#define INT_DIM 256
#define MT 64                   // rows per CTA (M) -- M-split for 2 CTAs/SM
#define NT 256                  // hidden per CTA (N)
#define KC 64                   // k per staged chunk
#define NCHUNK (ENC_DIM / KC)   // 4
#define NKS (KC / 16)           // 4 k16 steps per chunk
#define P 36                    // smem pitch in u32 words (32 used + 4 pad)
#define ASZ (MT * P)            // 2304 words
#define BSZ (NT * P)            // 9216 words
#define DYN_BYTES (2 * (ASZ + BSZ) * 4)   // 92160 -> 2 CTAs/SM
#define NTHR 256
#define NC 16                   // context chunks per batch

// Scratch (allocation-free rule: __device__ globals)
__device__ float  g_dp[64 * INT_DIM];          // dec_proj [B, I]
__device__ float  g_scores[64 * 2048];         // scores   [B, T]
__device__ float  g_w2t[ENC_DIM * INT_DIM];    // w2 transposed
__device__ __half g_w1h[INT_DIM * ENC_DIM];    // w1 as fp16, [n][k]
__device__ float  g_part[NC * 64 * ENC_DIM];   // context partials

// ---------------------------------------------------------------------------
// helpers
// ---------------------------------------------------------------------------
__device__ __forceinline__ float tanha(float x) {
    float y;
    asm("tanh.approx.f32 %0, %1;" : "=f"(y) : "f"(x));
    return y;
}
__device__ __forceinline__ void cp16(unsigned dst_s, const void* src) {
    asm volatile("cp.async.cg.shared.global [%0], [%1], 16;"
                 :: "r"(dst_s), "l"(src) : "memory");
}
__device__ __forceinline__ void cp_commit() {
    asm volatile("cp.async.commit_group;" ::: "memory");
}
template <int N>
__device__ __forceinline__ void cp_wait() {
    asm volatile("cp.async.wait_group %0;" :: "n"(N) : "memory");
}
__device__ __forceinline__ unsigned s2u(const void* p) {
    return (unsigned)__cvta_generic_to_shared(p);
}
__device__ __forceinline__ void ldsm4(unsigned r[4], unsigned addr) {
    asm volatile("ldmatrix.sync.aligned.m8n8.x4.shared.b16 "
                 "{%0,%1,%2,%3}, [%4];"
                 : "=r"(r[0]), "=r"(r[1]), "=r"(r[2]), "=r"(r[3])
                 : "r"(addr));
}
__device__ __forceinline__ void mma_f16(float d[4], const unsigned a[4],
                                        unsigned b0, unsigned b1) {
    asm volatile(
        "mma.sync.aligned.m16n8k16.row.col.f32.f16.f16.f32 "
        "{%0,%1,%2,%3}, {%4,%5,%6,%7}, {%8,%9}, {%0,%1,%2,%3};"
        : "+f"(d[0]), "+f"(d[1]), "+f"(d[2]), "+f"(d[3])
        : "r"(a[0]), "r"(a[1]), "r"(a[2]), "r"(a[3]), "r"(b0), "r"(b1));
}

// ---------------------------------------------------------------------------
// K0a: w1 -> fp16 (layout unchanged: [n][k])
// ---------------------------------------------------------------------------
__global__ void w1half_kernel(const float* __restrict__ w1,
                              __half* __restrict__ w1h) {
    const int i = blockIdx.x * 256 + threadIdx.x;
    w1h[i] = __float2half(w1[i]);
}

// ---------------------------------------------------------------------------
// K0b: transpose w2 (for decproj coalescing)
// ---------------------------------------------------------------------------
__global__ void transpose_w2_kernel(const float* __restrict__ w2,
                                    float* __restrict__ w2t) {
    __shared__ float tile[32][33];
    int x = blockIdx.x * 32 + threadIdx.x;
    int y = blockIdx.y * 32 + threadIdx.y;
#pragma unroll
    for (int dy = 0; dy < 32; dy += 8)
        tile[threadIdx.y + dy][threadIdx.x] = w2[(y + dy) * 256 + x];
    __syncthreads();
    x = blockIdx.y * 32 + threadIdx.x;
    y = blockIdx.x * 32 + threadIdx.y;
#pragma unroll
    for (int dy = 0; dy < 32; dy += 8)
        w2t[(y + dy) * 256 + x] = tile[threadIdx.x][threadIdx.y + dy];
}

// ---------------------------------------------------------------------------
// K1: dec_proj[b,i] = sum_k w2t[k,i] * dec[b,k]
// ---------------------------------------------------------------------------
__global__ void decproj_kernel(const float* __restrict__ dec,
                               const float* __restrict__ w2t,
                               float* __restrict__ dp) {
    __shared__ float ds[ENC_DIM];
    const int b = blockIdx.x;
    const int i = threadIdx.x;
    ds[i] = dec[b * ENC_DIM + i];
    __syncthreads();
    float acc = 0.f;
#pragma unroll 8
    for (int k = 0; k < ENC_DIM; ++k)
        acc = fmaf(__ldg(w2t + k * INT_DIM + i), ds[k], acc);
    dp[b * INT_DIM + i] = acc;
}

// ---------------------------------------------------------------------------
// K2: scores via fp16 mma m16n8k16 + ldmatrix. M-split: CTA = 64 rows x 256 n,
// 256 threads, 2 CTAs/SM (cross-CTA latency hiding; enc still read once).
// Warp w: m-half (w&1)*32 (h=2, B reused), n-quarter (w>>1)*64 (j=8).
// ---------------------------------------------------------------------------
__global__ void __launch_bounds__(NTHR, 2)
scores_mma_kernel(const float* __restrict__ enc,
                  const __half* __restrict__ w1h,
                  const float* __restrict__ dp,
                  const float* __restrict__ v,
                  float* __restrict__ scores,
                  int T) {
    extern __shared__ unsigned sm[];          // A0 | A1 | B0 | B1
    __shared__ float dps[INT_DIM], vs[INT_DIM], ssc[MT];

    const int tid  = threadIdx.x;
    const int wid  = tid >> 5;
    const int lane = tid & 31;
    const int t    = lane & 3;
    const int m0   = (wid & 1) * 32;
    const int nb   = (wid >> 1) * 64;
    const long long row0 = (long long)blockIdx.x * MT;
    const int b = (int)(row0 / T);

    dps[tid] = dp[b * INT_DIM + tid];
    vs[tid]  = __ldg(v + tid);
    if (tid < MT) ssc[tid] = 0.f;

    const unsigned smem_base = s2u(sm);

    // ldmatrix lane-dependent word offsets (within a buffer)
    const unsigned a_lane_off = (unsigned)((m0 + (lane & 15)) * P + ((lane >> 4) << 2));
    const unsigned b_lane_off = (unsigned)((nb + ((lane >> 4) & 1) * 8 + (lane & 7)) * P
                                           + ((lane >> 3) & 1) * 4);

    const int ar = tid >> 2;                  // A staging: row (0..63)
    const int aq = tid & 3;                   // A staging: quarter (16 floats)

    // stage B chunk c into buffer c&1 via cp.async (2048 cp16 / 256 thr = 8)
    auto stageB = [&](int c) {
        const int kc = c * KC;
        const unsigned bb = smem_base + (2 * ASZ + (c & 1) * BSZ) * 4;
#pragma unroll
        for (int i = tid; i < NT * 8; i += NTHR) {
            int n = i >> 3, q = i & 7;
            cp16(bb + (n * P + q * 4) * 4, w1h + n * ENC_DIM + kc + q * 8);
        }
    };

    float4 fr[4];                              // A prefetch regs (16 floats)
    auto ldgA = [&](int c) {
        const float4* src = reinterpret_cast<const float4*>(
            enc + (row0 + ar) * ENC_DIM + c * KC + aq * 16);
        fr[0] = src[0]; fr[1] = src[1]; fr[2] = src[2]; fr[3] = src[3];
    };
    auto stsA = [&](int c) {
        uint32_t w[8];
#pragma unroll
        for (int q = 0; q < 4; ++q) {
            __half2 h0 = __floats2half2_rn(fr[q].x, fr[q].y);
            __half2 h1 = __floats2half2_rn(fr[q].z, fr[q].w);
            w[2 * q]     = *reinterpret_cast<uint32_t*>(&h0);
            w[2 * q + 1] = *reinterpret_cast<uint32_t*>(&h1);
        }
        uint4* dst = reinterpret_cast<uint4*>(
            sm + (c & 1) * ASZ + ar * P + aq * 8);
        dst[0] = make_uint4(w[0], w[1], w[2], w[3]);
        dst[1] = make_uint4(w[4], w[5], w[6], w[7]);
    };

    float d[2][8][4];
#pragma unroll
    for (int h = 0; h < 2; ++h)
#pragma unroll
        for (int j = 0; j < 8; ++j)
#pragma unroll
            for (int q = 0; q < 4; ++q) d[h][j][q] = 0.f;

    // prologue: B0,B1 in flight; A0 staged; regs hold A1
    stageB(0); cp_commit();
    stageB(1); cp_commit();
    ldgA(0);
    stsA(0);
    ldgA(1);
    cp_wait<1>();                              // B0 arrived
    __syncthreads();

    for (int c = 0; c < NCHUNK; ++c) {
        const int p = c & 1;
        const unsigned abase = smem_base + (p * ASZ) * 4 + a_lane_off * 4;
        const unsigned bbase = smem_base + (2 * ASZ + p * BSZ) * 4 + b_lane_off * 4;

#pragma unroll
        for (int s = 0; s < NKS; ++s) {        // four k16 steps per chunk
            unsigned a[2][4];
            ldsm4(a[0], abase + (s * 8) * 4);
            ldsm4(a[1], abase + (16 * P + s * 8) * 4);
#pragma unroll
            for (int jp = 0; jp < 4; ++jp) {   // j-pairs {0,1},{2,3},{4,5},{6,7}
                unsigned bb[4];
                ldsm4(bb, bbase + (jp * 16 * P + s * 8) * 4);
                mma_f16(d[0][2 * jp],     a[0], bb[0], bb[1]);
                mma_f16(d[1][2 * jp],     a[1], bb[0], bb[1]);
                mma_f16(d[0][2 * jp + 1], a[0], bb[2], bb[3]);
                mma_f16(d[1][2 * jp + 1], a[1], bb[2], bb[3]);
            }
        }

        if (c + 1 < NCHUNK) stsA(c + 1);       // writes buffer 1-p: safe
        __syncthreads();                        // chunk c fully consumed
        if (c + 2 < NCHUNK) {
            ldgA(c + 2);
            stageB(c + 2); cp_commit();        // writes buffer p: now safe
            cp_wait<1>();                      // B(c+1) arrived
        } else {
            cp_wait<0>();
        }
        __syncthreads();                        // staged data visible to all
    }

    // Epilogue: +dec_proj, tanh.approx, *v, warp-reduce n, 4-way smem combine
    const int g = lane >> 2;
#pragma unroll
    for (int h = 0; h < 2; ++h) {
        float s0 = 0.f, s1 = 0.f;
#pragma unroll
        for (int j = 0; j < 8; ++j) {
            const int n0 = nb + 8 * j + 2 * t;
            const float vv0 = vs[n0],  vv1 = vs[n0 + 1];
            const float dd0 = dps[n0], dd1 = dps[n0 + 1];
            s0 += vv0 * tanha(d[h][j][0] + dd0) + vv1 * tanha(d[h][j][1] + dd1);
            s1 += vv0 * tanha(d[h][j][2] + dd0) + vv1 * tanha(d[h][j][3] + dd1);
        }
        s0 += __shfl_xor_sync(0xffffffffu, s0, 1);
        s0 += __shfl_xor_sync(0xffffffffu, s0, 2);
        s1 += __shfl_xor_sync(0xffffffffu, s1, 1);
        s1 += __shfl_xor_sync(0xffffffffu, s1, 2);
        if (t == 0) {
            atomicAdd(&ssc[m0 + 16 * h + g], s0);
            atomicAdd(&ssc[m0 + 16 * h + 8 + g], s1);
        }
    }
    __syncthreads();
    if (tid < MT) scores[row0 + tid] = ssc[tid];
}

// ---------------------------------------------------------------------------
// K3: per-batch softmax over T -> probs (out[B*256 ..])
// ---------------------------------------------------------------------------
__global__ void softmax_kernel(const float* __restrict__ scores,
                               float* __restrict__ out,
                               int B, int T) {
    extern __shared__ float ss[];
    __shared__ float red[8];
    const int b = blockIdx.x;
    const int tid = threadIdx.x;
    const int lane = tid & 31, wid = tid >> 5;

    for (int t = tid; t < T; t += 256) ss[t] = scores[b * T + t];
    __syncthreads();

    float m = -CUDART_INF_F;
    for (int t = tid; t < T; t += 256) m = fmaxf(m, ss[t]);
#pragma unroll
    for (int o = 16; o; o >>= 1) m = fmaxf(m, __shfl_xor_sync(0xffffffffu, m, o));
    if (lane == 0) red[wid] = m;
    __syncthreads();
    if (tid == 0) {
        float mm = red[0];
#pragma unroll
        for (int w = 1; w < 8; ++w) mm = fmaxf(mm, red[w]);
        red[0] = mm;
    }
    __syncthreads();
    m = red[0];
    __syncthreads();

    float z = 0.f;
    for (int t = tid; t < T; t += 256) z += expf(ss[t] - m);
#pragma unroll
    for (int o = 16; o; o >>= 1) z += __shfl_xor_sync(0xffffffffu, z, o);
    if (lane == 0) red[wid] = z;
    __syncthreads();
    if (tid == 0) {
        float zz = 0.f;
#pragma unroll
        for (int w = 0; w < 8; ++w) zz += red[w];
        red[0] = zz;
    }
    __syncthreads();
    const float inv = 1.f / red[0];

    float* probs = out + (long long)B * ENC_DIM;
    for (int t = tid; t < T; t += 256)
        probs[(long long)b * T + t] = expf(ss[t] - m) * inv;
}

// ---------------------------------------------------------------------------
// K4: context partials. grid (B, NC). 4 accumulators for MLP.
// ---------------------------------------------------------------------------
__global__ void ctx_partial_kernel(const float* __restrict__ enc,
                                   const float* __restrict__ out_probs,
                                   float* __restrict__ part,
                                   int B, int T) {
    __shared__ float ps[2048 / NC];
    const int b = blockIdx.x;
    const int c = blockIdx.y;
    const int tid = threadIdx.x;
    const int TC = T / NC;                       // 128
    const long long t0 = (long long)c * TC;

    if (tid < TC) ps[tid] = out_probs[(long long)b * T + t0 + tid];
    __syncthreads();

    float a0 = 0.f, a1 = 0.f, a2 = 0.f, a3 = 0.f;
    const float* e = enc + ((long long)b * T + t0) * ENC_DIM + tid;
#pragma unroll 8
    for (int t = 0; t < TC; t += 4) {
        a0 = fmaf(ps[t],     __ldg(e + (long long)t * ENC_DIM),       a0);
        a1 = fmaf(ps[t + 1], __ldg(e + (long long)(t + 1) * ENC_DIM), a1);
        a2 = fmaf(ps[t + 2], __ldg(e + (long long)(t + 2) * ENC_DIM), a2);
        a3 = fmaf(ps[t + 3], __ldg(e + (long long)(t + 3) * ENC_DIM), a3);
    }
    part[((long long)c * B + b) * ENC_DIM + tid] = (a0 + a1) + (a2 + a3);
}

// ---------------------------------------------------------------------------
// K5: reduce partials -> out context region
// ---------------------------------------------------------------------------
__global__ void ctx_reduce_kernel(const float* __restrict__ part,
                                  float* __restrict__ out, int B) {
    const int b = blockIdx.x;
    const int tid = threadIdx.x;
    float acc = 0.f;
#pragma unroll
    for (int c = 0; c < NC; ++c)
        acc += part[((long long)c * B + b) * ENC_DIM + tid];
    out[b * ENC_DIM + tid] = acc;
}

// ---------------------------------------------------------------------------
extern "C" void kernel_launch(void* const* d_in, const int* in_sizes, int n_in,
                              void* d_out, int out_size) {
    const float* enc = (const float*)d_in[0];   // [B,T,256]
    const float* dec = (const float*)d_in[1];   // [B,256]
    const float* w1  = (const float*)d_in[2];   // [256,256]
    const float* w2  = (const float*)d_in[3];   // [256,256]
    const float* v   = (const float*)d_in[4];   // [1,256]
    float* out = (float*)d_out;

    const int B = in_sizes[1] / ENC_DIM;                 // 64
    const int T = in_sizes[0] / (B * ENC_DIM);           // 2048

    float*  dp_ptr;     cudaGetSymbolAddress((void**)&dp_ptr, g_dp);
    float*  scores_ptr; cudaGetSymbolAddress((void**)&scores_ptr, g_scores);
    float*  w2t_ptr;    cudaGetSymbolAddress((void**)&w2t_ptr, g_w2t);
    __half* w1h_ptr;    cudaGetSymbolAddress((void**)&w1h_ptr, g_w1h);
    float*  part_ptr;   cudaGetSymbolAddress((void**)&part_ptr, g_part);

    cudaFuncSetAttribute(scores_mma_kernel,
                         cudaFuncAttributeMaxDynamicSharedMemorySize, DYN_BYTES);

    w1half_kernel<<<INT_DIM * ENC_DIM / 256, 256>>>(w1, w1h_ptr);
    transpose_w2_kernel<<<dim3(8, 8), dim3(32, 8)>>>(w2, w2t_ptr);
    decproj_kernel<<<B, 256>>>(dec, w2t_ptr, dp_ptr);
    scores_mma_kernel<<<(B * T) / MT, NTHR, DYN_BYTES>>>(enc, w1h_ptr, dp_ptr, v,
                                                         scores_ptr, T);
    softmax_kernel<<<B, 256, T * (int)sizeof(float)>>>(scores_ptr, out, B, T);
    ctx_partial_kernel<<<dim3(B, NC), 256>>>(enc, out + (long long)B * ENC_DIM,
                                             part_ptr, B, T);
    ctx_reduce_kernel<<<B, 256>>>(part_ptr, out, B);
}